// round 17
// baseline (speedup 1.0000x reference)
#include <cuda_runtime.h>
#include <cuda_fp16.h>
#include <cstdint>
#include <math.h>

// Problem constants
#define BATCH   4
#define SEQ_N   2048
#define SEQ_J   2048
#define DIM     768
#define HEADS   12
#define DHEAD   64
#define INNER   (HEADS * DHEAD)   // 768
#define SCALE   0.125f            // 64^-0.5

#define ROWS_TOTAL (BATCH * SEQ_N) // 8192

// ---------------------------------------------------------------------------
// Scratch (static device allocations; no cudaMalloc allowed)
// ---------------------------------------------------------------------------
__device__ __half g_xnh [(size_t)ROWS_TOTAL * DIM];    // layernorm(x), fp16
__device__ __half g_ctxh[(size_t)ROWS_TOTAL * DIM];    // context, fp16
__device__ __half g_qh  [(size_t)ROWS_TOTAL * INNER];  // q, fp16, pre-scaled
__device__ __half g_kvh [(size_t)ROWS_TOTAL * 128];    // [k|v] fp16
__device__ __half g_aoh [(size_t)ROWS_TOTAL * INNER];  // attn output, fp16
__device__ __half g_wqh [DIM * INNER];                 // Wq fp16
__device__ __half g_wkvh[DIM * 128];                   // Wkv fp16
__device__ __half g_woh [INNER * DIM];                 // Wo fp16

// ===========================================================================
// helpers (sm_80+ portable PTX — compiles for plain sm_103)
// ===========================================================================
__device__ __forceinline__ void mma_f16(float* d, const uint32_t* a,
                                        uint32_t b0, uint32_t b1) {
    asm volatile(
        "mma.sync.aligned.m16n8k16.row.col.f32.f16.f16.f32 "
        "{%0,%1,%2,%3}, {%4,%5,%6,%7}, {%8,%9}, {%0,%1,%2,%3};"
        : "+f"(d[0]), "+f"(d[1]), "+f"(d[2]), "+f"(d[3])
        : "r"(a[0]), "r"(a[1]), "r"(a[2]), "r"(a[3]), "r"(b0), "r"(b1));
}
__device__ __forceinline__ uint32_t smem_to_u32(const void* p) {
    uint32_t a;
    asm("{ .reg .u64 t; cvta.to.shared.u64 t, %1; cvt.u32.u64 %0, t; }"
        : "=r"(a) : "l"(p));
    return a;
}
__device__ __forceinline__ uint32_t h2bits(__half2 h) {
    return *reinterpret_cast<uint32_t*>(&h);
}
#define CP_ASYNC16(dst_u32, src_ptr) \
    asm volatile("cp.async.cg.shared.global [%0], [%1], 16;" \
        :: "r"(dst_u32), "l"(src_ptr))
#define CP_COMMIT() asm volatile("cp.async.commit_group;" ::: "memory")
#define CP_WAIT_ALL() asm volatile("cp.async.wait_group 0;" ::: "memory")
#define CP_WAIT_1()   asm volatile("cp.async.wait_group 1;" ::: "memory")

#define LDSM_X4(r0, r1, r2, r3, addr) \
    asm volatile("ldmatrix.sync.aligned.m8n8.x4.shared.b16 {%0,%1,%2,%3}, [%4];" \
        : "=r"(r0), "=r"(r1), "=r"(r2), "=r"(r3) : "r"(addr))
#define LDSM_X4_T(r0, r1, r2, r3, addr) \
    asm volatile("ldmatrix.sync.aligned.m8n8.x4.trans.shared.b16 {%0,%1,%2,%3}, [%4];" \
        : "=r"(r0), "=r"(r1), "=r"(r2), "=r"(r3) : "r"(addr))

// ---------------------------------------------------------------------------
// LayerNorm: one block per row of 768, fp16 output
// ---------------------------------------------------------------------------
__global__ void ln_kernel(const float* __restrict__ x,
                          const float* __restrict__ w,
                          __half* __restrict__ y)
{
    const int row = blockIdx.x;
    const float* xr = x + (size_t)row * DIM;
    float v[3];
    float s = 0.f, s2 = 0.f;
#pragma unroll
    for (int t = 0; t < 3; t++) {
        int i = threadIdx.x + t * 256;
        float vv = xr[i];
        v[t] = vv;
        s += vv; s2 += vv * vv;
    }
#pragma unroll
    for (int o = 16; o > 0; o >>= 1) {
        s  += __shfl_xor_sync(0xffffffffu, s,  o);
        s2 += __shfl_xor_sync(0xffffffffu, s2, o);
    }
    __shared__ float rs[8], rs2[8];
    int wid = threadIdx.x >> 5, lid = threadIdx.x & 31;
    if (lid == 0) { rs[wid] = s; rs2[wid] = s2; }
    __syncthreads();
    if (wid == 0) {
        s  = (lid < 8) ? rs[lid]  : 0.f;
        s2 = (lid < 8) ? rs2[lid] : 0.f;
#pragma unroll
        for (int o = 4; o > 0; o >>= 1) {
            s  += __shfl_xor_sync(0xffffffffu, s,  o);
            s2 += __shfl_xor_sync(0xffffffffu, s2, o);
        }
        if (lid == 0) { rs[0] = s; rs2[0] = s2; }
    }
    __syncthreads();
    const float mu   = rs[0] * (1.f / DIM);
    const float var  = rs2[0] * (1.f / DIM) - mu * mu;
    const float rstd = rsqrtf(var + 1e-5f);
    __half* yr = y + (size_t)row * DIM;
#pragma unroll
    for (int t = 0; t < 3; t++) {
        int i = threadIdx.x + t * 256;
        yr[i] = __float2half_rn((v[t] - mu) * rstd * w[i]);
    }
}

// ---------------------------------------------------------------------------
// fused fp32 -> fp16 convert: four segments in ONE launch
// ---------------------------------------------------------------------------
__global__ void cvt_all_kernel(const float* s0, __half* d0, int n0,
                               const float* s1, __half* d1, int n1,
                               const float* s2, __half* d2, int n2,
                               const float* s3, __half* d3, int n3)
{
    int i = blockIdx.x * blockDim.x + threadIdx.x;
    const float* src;
    __half* dst;
    if (i < n0) { src = s0; dst = d0; }
    else if ((i -= n0) < n1) { src = s1; dst = d1; }
    else if ((i -= n1) < n2) { src = s2; dst = d2; }
    else if ((i -= n2) < n3) { src = s3; dst = d3; }
    else return;
    float4 v = reinterpret_cast<const float4*>(src)[i];
    reinterpret_cast<uint2*>(dst)[i] =
        make_uint2(h2bits(__floats2half2_rn(v.x, v.y)),
                   h2bits(__floats2half2_rn(v.z, v.w)));
}

// ---------------------------------------------------------------------------
// fp16 tensor-core GEMM (all operands fp16), cp.async 3-stage pipeline.
// Dual-job: blockIdx.x < nx0 -> job0, else job1.  (unchanged from round 14)
// ---------------------------------------------------------------------------
#define AST 40
#define A_STG_B 10240
#define B_STG_B 8192
#define GEMM_SMEM_BYTES (3 * (A_STG_B + B_STG_B))   // 55296

struct GemmJob {
    const __half* A;
    const __half* B;
    void*         C;
    int N, K, out_mode;
};

__device__ __forceinline__ void gemm_stage(uint32_t sbase, int stg,
                                           const __half* A, const __half* B,
                                           int m0, int n0, int kt,
                                           int N, int K, int tid)
{
    const uint32_t ab = sbase + stg * (A_STG_B + B_STG_B);
    const uint32_t bb = ab + A_STG_B;
#pragma unroll
    for (int t = 0; t < 2; t++) {
        const int e = tid + t * 256;
        const int ar = e >> 2, ac = e & 3;
        CP_ASYNC16(ab + (uint32_t)(ar * 80 + ac * 16),
                   &A[(size_t)(m0 + ar) * K + kt + ac * 8]);
        const int bk = e >> 4, bc = e & 15;
        CP_ASYNC16(bb + (uint32_t)(bk * 256 + ((bc ^ (bk & 7)) * 16)),
                   &B[(size_t)(kt + bk) * N + n0 + bc * 8]);
    }
    CP_COMMIT();
}

__global__ __launch_bounds__(256, 2)
void gemm_dual_kernel(GemmJob j0, int nx0, GemmJob j1)
{
    extern __shared__ char gsm[];
    const uint32_t sbase = smem_to_u32(gsm);

    GemmJob jb;
    int bx;
    if ((int)blockIdx.x < nx0) { jb = j0; bx = blockIdx.x; }
    else                       { jb = j1; bx = blockIdx.x - nx0; }
    const int N = jb.N;
    const int K = jb.K;

    const int tid  = threadIdx.x;
    const int wid  = tid >> 5;
    const int lane = tid & 31;
    const int g8   = lane >> 3;
    const int r8   = lane & 7;
    const int gr   = lane >> 2;
    const int gq   = lane & 3;
    const int wm   = (wid & 3) * 32;
    const int wn   = (wid >> 2) * 64;
    const int m0   = blockIdx.y * 128;
    const int n0   = bx * 128;

    float acc[2][8][4];
#pragma unroll
    for (int ms = 0; ms < 2; ms++)
#pragma unroll
        for (int nt = 0; nt < 8; nt++)
#pragma unroll
            for (int i = 0; i < 4; i++) acc[ms][nt][i] = 0.f;

    const uint32_t arow  = (uint32_t)(wm + ((g8 & 1) << 3) + r8);
    const uint32_t akc   = (uint32_t)(g8 >> 1);
    const uint32_t bkrow = (uint32_t)(((g8 & 1) << 3) + r8);
    const uint32_t bnc   = (uint32_t)((wn >> 3) + (g8 >> 1));

    const int niter = K / 32;

    gemm_stage(sbase, 0, jb.A, jb.B, m0, n0, 0,  N, K, tid);
    gemm_stage(sbase, 1, jb.A, jb.B, m0, n0, 32, N, K, tid);

    int stg = 0;
    for (int it = 0; it < niter; it++) {
        CP_WAIT_1();
        __syncthreads();

        if (it + 2 < niter)
            gemm_stage(sbase, (stg + 2) % 3, jb.A, jb.B, m0, n0,
                       (it + 2) * 32, N, K, tid);

        const uint32_t ab = sbase + stg * (A_STG_B + B_STG_B);
        const uint32_t bb = ab + A_STG_B;

#pragma unroll
        for (int c = 0; c < 2; c++) {
            uint32_t af[2][4];
#pragma unroll
            for (int ms = 0; ms < 2; ms++) {
                const uint32_t a = ab + (arow + ms * 16) * 80
                                 + (c * 2 + akc) * 16;
                LDSM_X4(af[ms][0], af[ms][1], af[ms][2], af[ms][3], a);
            }
            uint32_t bf[8][2];
#pragma unroll
            for (int ntp = 0; ntp < 4; ntp++) {
                const uint32_t row = (uint32_t)(c * 16) + bkrow;
                const uint32_t a = bb + row * 256
                                 + (((bnc + ntp * 2) ^ (uint32_t)r8) << 4);
                LDSM_X4_T(bf[2 * ntp][0], bf[2 * ntp][1],
                          bf[2 * ntp + 1][0], bf[2 * ntp + 1][1], a);
            }
#pragma unroll
            for (int nt = 0; nt < 8; nt++)
#pragma unroll
                for (int ms = 0; ms < 2; ms++)
                    mma_f16(acc[ms][nt], af[ms], bf[nt][0], bf[nt][1]);
        }
        stg = (stg + 1) % 3;
    }

    const float alpha = (jb.out_mode == 2) ? SCALE : 1.0f;
    float*  Cf = reinterpret_cast<float*>(jb.C);
    __half* Ch = reinterpret_cast<__half*>(jb.C);
#pragma unroll
    for (int ms = 0; ms < 2; ms++) {
        const int mrow0 = m0 + wm + ms * 16 + gr;
#pragma unroll
        for (int nt = 0; nt < 8; nt++) {
            const int col = n0 + wn + nt * 8 + 2 * gq;
            if (jb.out_mode == 0) {
                *reinterpret_cast<float2*>(&Cf[(size_t)mrow0 * N + col]) =
                    make_float2(acc[ms][nt][0], acc[ms][nt][1]);
                *reinterpret_cast<float2*>(&Cf[(size_t)(mrow0 + 8) * N + col]) =
                    make_float2(acc[ms][nt][2], acc[ms][nt][3]);
            } else {
                *reinterpret_cast<__half2*>(&Ch[(size_t)mrow0 * N + col]) =
                    __floats2half2_rn(acc[ms][nt][0] * alpha,
                                      acc[ms][nt][1] * alpha);
                *reinterpret_cast<__half2*>(&Ch[(size_t)(mrow0 + 8) * N + col]) =
                    __floats2half2_rn(acc[ms][nt][2] * alpha,
                                      acc[ms][nt][3] * alpha);
            }
        }
    }
}

// ---------------------------------------------------------------------------
// fp16 mma.sync flash attention — multi-query, 32 rows/warp, 8 warps/CTA.
// CTA = (b, 64 q-rows, 4-head group), 256 threads. Warp w: head hg*4+(w&3),
// rows row0 + (w>>2)*32 .. +31 (two 16-row M-tiles). K/V + mask staged ONCE
// per CTA serve all 8 warps (2x less staging/L2 vs 4-warp CTA). 3-stage
// cp.async pipeline (two tiles in flight). P in registers (FA2). 1 CTA/SM.
// ---------------------------------------------------------------------------
#define MOFF   16384
#define MROWB  272                       // mask row stride bytes (68 floats)
#define STG_B  (16384 + 64 * MROWB)      // 33792
#define ATTN_SMEM_BYTES (3 * STG_B)      // 101376
#define NTILES (SEQ_J / 64)              // 32

__device__ __forceinline__ void stage_kvm(uint32_t sbase, int stg,
                                          const __half* kv_tile,
                                          const float* mask_tile, int tid)
{
    const uint32_t base = sbase + stg * STG_B;
    // K/V: 64 rows x 256B = 1024 chunks, 256 threads -> 4 each
#pragma unroll
    for (int t = 0; t < 4; t++) {
        const int e   = tid + t * 256;
        const int jj  = e >> 4;
        const int c16 = e & 15;
        const char* src = reinterpret_cast<const char*>(kv_tile)
                          + (size_t)jj * 256 + c16 * 16;
        const uint32_t sw = (uint32_t)(jj & 7) << 4;
        const uint32_t dst = (c16 < 8)
            ? base + (uint32_t)jj * 128 + (((uint32_t)c16 * 16) ^ sw)
            : base + 8192 + (uint32_t)jj * 128 + (((uint32_t)(c16 - 8) * 16) ^ sw);
        CP_ASYNC16(dst, src);
    }
    // mask: 64 rows x 256B = 1024 chunks -> 4 each
#pragma unroll
    for (int t = 0; t < 4; t++) {
        const int e = tid + t * 256;
        const int r = e >> 4;
        const int c = e & 15;
        CP_ASYNC16(base + MOFF + (uint32_t)(r * MROWB + c * 16),
                   &mask_tile[(size_t)r * SEQ_J + c * 4]);
    }
    CP_COMMIT();
}

__global__ __launch_bounds__(256, 1)
void attn_f16_kernel(const __half* __restrict__ q,
                     const __half* __restrict__ kv,
                     const float* __restrict__ mask, __half* __restrict__ o)
{
    extern __shared__ char smc[];
    const uint32_t sbase = smem_to_u32(smc);

    const int tid  = threadIdx.x;
    const int wid  = tid >> 5;
    const int lane = tid & 31;
    const int gr   = lane >> 2;
    const int gq   = lane & 3;
    const int g8   = lane >> 3;
    const int r8   = lane & 7;
    const int h    = blockIdx.y * 4 + (wid & 3);
    const int b    = blockIdx.z;
    const int rowc = blockIdx.x * 64;              // CTA row base
    const int row0 = rowc + (wid >> 2) * 32;       // warp row base

    // ---- Q fragments: 2 M-tiles x 4 k-steps x 4 regs ----
    uint32_t qf[2][4][4];
#pragma unroll
    for (int ms = 0; ms < 2; ms++) {
        const __half* qb = q + ((size_t)(b * SEQ_N) + row0 + ms * 16) * INNER
                           + h * DHEAD;
#pragma unroll
        for (int c = 0; c < 4; c++) {
            qf[ms][c][0] = *reinterpret_cast<const uint32_t*>(
                &qb[(size_t)(gr    ) * INNER + c * 16 + 2 * gq]);
            qf[ms][c][1] = *reinterpret_cast<const uint32_t*>(
                &qb[(size_t)(gr + 8) * INNER + c * 16 + 2 * gq]);
            qf[ms][c][2] = *reinterpret_cast<const uint32_t*>(
                &qb[(size_t)(gr    ) * INNER + c * 16 + 8 + 2 * gq]);
            qf[ms][c][3] = *reinterpret_cast<const uint32_t*>(
                &qb[(size_t)(gr + 8) * INNER + c * 16 + 8 + 2 * gq]);
        }
    }

    float oacc[2][8][4];
#pragma unroll
    for (int ms = 0; ms < 2; ms++)
#pragma unroll
        for (int nt = 0; nt < 8; nt++)
#pragma unroll
            for (int i = 0; i < 4; i++) oacc[ms][nt][i] = 0.f;
    float lsum[2][2] = {{0.f, 0.f}, {0.f, 0.f}};   // [ms][half]

    const __half* kv_base = kv + (size_t)b * SEQ_J * 128;
    const float* mask_base = mask + ((size_t)(b * SEQ_N) + rowc) * SEQ_J;

    const uint32_t kj    = (uint32_t)(((g8 >> 1) << 3) + r8);
    const uint32_t kcsel = (uint32_t)(g8 & 1);
    const uint32_t vj    = (uint32_t)(((g8 & 1) << 3) + r8);
    const uint32_t vcsel = (uint32_t)(g8 >> 1);
    const uint32_t mwarp = (uint32_t)(((wid >> 2) * 32 + gr) * MROWB + gq * 8);

    // ---- prologue: two tiles in flight ----
    stage_kvm(sbase, 0, kv_base, mask_base, tid);
    stage_kvm(sbase, 1, kv_base + 64 * 128, mask_base + 64, tid);

    int stg = 0;
#pragma unroll 1
    for (int t = 0; t < NTILES; t++) {
        CP_WAIT_1();          // tile t landed
        __syncthreads();      // visible; all warps done with stage t-1's buf

        if (t + 2 < NTILES)
            stage_kvm(sbase, (stg + 2) % 3,
                      kv_base + (size_t)(t + 2) * 64 * 128,
                      mask_base + (size_t)(t + 2) * 64, tid);

        const uint32_t Kb = sbase + stg * STG_B;
        const uint32_t Vb = Kb + 8192;
        const char* Mb = smc + stg * STG_B + MOFF;

        // ---- S = Q @ K^T : each K fragment feeds both M-tiles ----
        float sacc[2][8][4];
#pragma unroll
        for (int ms = 0; ms < 2; ms++)
#pragma unroll
            for (int nt = 0; nt < 8; nt++)
#pragma unroll
                for (int i = 0; i < 4; i++) sacc[ms][nt][i] = 0.f;

#pragma unroll
        for (int c = 0; c < 4; c++) {
            uint32_t kb2[8][2];
#pragma unroll
            for (int ntp = 0; ntp < 4; ntp++) {
                const uint32_t a = Kb + (ntp * 16 + kj) * 128
                    + ((((uint32_t)(c * 2) + kcsel) ^ (uint32_t)r8) << 4);
                LDSM_X4(kb2[2 * ntp][0], kb2[2 * ntp][1],
                        kb2[2 * ntp + 1][0], kb2[2 * ntp + 1][1], a);
            }
#pragma unroll
            for (int nt = 0; nt < 8; nt++)
#pragma unroll
                for (int ms = 0; ms < 2; ms++)
                    mma_f16(sacc[ms][nt], qf[ms][c], kb2[nt][0], kb2[nt][1]);
        }

        // ---- softmax (unstabilized), mask from smem; P -> A-fragments ----
        uint32_t pah[2][8][2];
#pragma unroll
        for (int ms = 0; ms < 2; ms++) {
            const uint32_t m0off = mwarp + (uint32_t)(ms * 16) * MROWB;
#pragma unroll
            for (int nt = 0; nt < 8; nt++) {
                float2 mk0 = *reinterpret_cast<const float2*>(
                    Mb + m0off + nt * 32);
                float2 mk1 = *reinterpret_cast<const float2*>(
                    Mb + m0off + 8 * MROWB + nt * 32);
                float p00 = __expf(sacc[ms][nt][0] + mk0.x);
                float p01 = __expf(sacc[ms][nt][1] + mk0.y);
                float p10 = __expf(sacc[ms][nt][2] + mk1.x);
                float p11 = __expf(sacc[ms][nt][3] + mk1.y);
                lsum[ms][0] += p00 + p01;
                lsum[ms][1] += p10 + p11;
                pah[ms][nt][0] = h2bits(__floats2half2_rn(p00, p01));
                pah[ms][nt][1] = h2bits(__floats2half2_rn(p10, p11));
            }
        }

        // ---- O += P @ V : each V fragment feeds both M-tiles ----
#pragma unroll
        for (int c = 0; c < 4; c++) {
            uint32_t vb2[8][2];
#pragma unroll
            for (int ntp = 0; ntp < 4; ntp++) {
                const uint32_t a = Vb + (c * 16 + vj) * 128
                    + ((((uint32_t)(ntp * 2) + vcsel) ^ (uint32_t)r8) << 4);
                LDSM_X4_T(vb2[2 * ntp][0], vb2[2 * ntp][1],
                          vb2[2 * ntp + 1][0], vb2[2 * ntp + 1][1], a);
            }
#pragma unroll
            for (int ms = 0; ms < 2; ms++) {
                uint32_t pa[4] = { pah[ms][2 * c][0], pah[ms][2 * c][1],
                                   pah[ms][2 * c + 1][0], pah[ms][2 * c + 1][1] };
#pragma unroll
                for (int nt = 0; nt < 8; nt++)
                    mma_f16(oacc[ms][nt], pa, vb2[nt][0], vb2[nt][1]);
            }
        }
        stg = (stg + 1) % 3;
    }

    // ---- finalize: reduce l over quad lanes, normalize, store ----
#pragma unroll
    for (int ms = 0; ms < 2; ms++) {
        float l0 = lsum[ms][0], l1 = lsum[ms][1];
        l0 += __shfl_xor_sync(0xffffffffu, l0, 1);
        l0 += __shfl_xor_sync(0xffffffffu, l0, 2);
        l1 += __shfl_xor_sync(0xffffffffu, l1, 1);
        l1 += __shfl_xor_sync(0xffffffffu, l1, 2);
        const float inv0 = 1.f / l0;
        const float inv1 = 1.f / l1;

        __half* ob = o + ((size_t)(b * SEQ_N) + row0 + ms * 16) * INNER
                     + h * DHEAD;
#pragma unroll
        for (int nt = 0; nt < 8; nt++) {
            const int cb = nt * 8 + 2 * gq;
            *reinterpret_cast<__half2*>(&ob[(size_t)gr * INNER + cb]) =
                __floats2half2_rn(oacc[ms][nt][0] * inv0,
                                  oacc[ms][nt][1] * inv0);
            *reinterpret_cast<__half2*>(&ob[(size_t)(gr + 8) * INNER + cb]) =
                __floats2half2_rn(oacc[ms][nt][2] * inv1,
                                  oacc[ms][nt][3] * inv1);
        }
    }
}

// ---------------------------------------------------------------------------
// Launch
// ---------------------------------------------------------------------------
extern "C" void kernel_launch(void* const* d_in, const int* in_sizes, int n_in,
                              void* d_out, int out_size)
{
    const float* x       = (const float*)d_in[0];
    const float* context = (const float*)d_in[1];
    const float* mask    = (const float*)d_in[2];
    const float* ln_w    = (const float*)d_in[3];
    const float* Wq      = (const float*)d_in[4];
    const float* Wkv     = (const float*)d_in[5];
    const float* Wo      = (const float*)d_in[6];
    float* out = (float*)d_out;

    __half *xnh, *ctxh, *qh, *kvh, *aoh, *wqh, *wkvh, *woh;
    cudaGetSymbolAddress((void**)&xnh,  g_xnh);
    cudaGetSymbolAddress((void**)&ctxh, g_ctxh);
    cudaGetSymbolAddress((void**)&qh,   g_qh);
    cudaGetSymbolAddress((void**)&kvh,  g_kvh);
    cudaGetSymbolAddress((void**)&aoh,  g_aoh);
    cudaGetSymbolAddress((void**)&wqh,  g_wqh);
    cudaGetSymbolAddress((void**)&wkvh, g_wkvh);
    cudaGetSymbolAddress((void**)&woh,  g_woh);

    cudaFuncSetAttribute(attn_f16_kernel,
                         cudaFuncAttributeMaxDynamicSharedMemorySize,
                         ATTN_SMEM_BYTES);
    cudaFuncSetAttribute(gemm_dual_kernel,
                         cudaFuncAttributeMaxDynamicSharedMemorySize,
                         GEMM_SMEM_BYTES);

    // 0. one fused convert launch: Wq, Wkv, Wo, context -> fp16
    {
        const int n0 = DIM * INNER / 4;        // 147456
        const int n1 = DIM * 128 / 4;          // 24576
        const int n2 = INNER * DIM / 4;        // 147456
        const int n3 = ROWS_TOTAL * DIM / 4;   // 1572864
        const int total = n0 + n1 + n2 + n3;
        cvt_all_kernel<<<(total + 255) / 256, 256>>>(
            Wq, wqh, n0, Wkv, wkvh, n1, Wo, woh, n2, context, ctxh, n3);
    }

    // 1. layernorm -> fp16
    ln_kernel<<<ROWS_TOTAL, 256>>>(x, ln_w, xnh);

    // 2+3. fused: Wq projection (6 x-tiles) + kv projection (1 x-tile)
    {
        GemmJob jq  = { xnh,  wqh,  qh,  INNER, DIM, 2 };
        GemmJob jkv = { ctxh, wkvh, kvh, 128,   DIM, 1 };
        gemm_dual_kernel<<<dim3(7, ROWS_TOTAL / 128), 256, GEMM_SMEM_BYTES>>>(
            jq, 6, jkv);
    }

    // 4. attention: CTA = 64 rows x 4 heads, 8 warps, 3-stage pipeline
    attn_f16_kernel<<<dim3(SEQ_N / 64, HEADS / 4, BATCH), 256,
                      ATTN_SMEM_BYTES>>>(qh, kvh, mask, aoh);

    // 5. out = ao @ Wo -> fp32
    {
        GemmJob jo = { aoh, woh, out, DIM, INNER, 0 };
        gemm_dual_kernel<<<dim3(6, ROWS_TOTAL / 128), 256, GEMM_SMEM_BYTES>>>(
            jo, 6, jo);
    }
}